// round 14
// baseline (speedup 1.0000x reference)
#include <cuda_runtime.h>
#include <cuda_fp16.h>
#include <math.h>
#include <cstdint>

#define BSZ 4
#define LSEQ 4096
#define DD 1024
#define CH 64
#define NCH (LSEQ / CH)
#define MROWS (BSZ * LSEQ)

// ---------------------------------------------------------------------------
// Scratch (device globals)
// ---------------------------------------------------------------------------
__device__ __half g_uh[(size_t)MROWS * 2 * DD];        // GEMM1 out, fp16 interleaved complex
__device__ float2 g_last[BSZ * NCH * DD];
__device__ float2 g_cin[BSZ * NCH * DD];

__device__ __half g_inh[(size_t)MROWS * DD];           // inputs fp16
__device__ __half g_wih[(size_t)2 * DD * DD];          // Wi fp16
__device__ __half g_woh[(size_t)DD * 2 * DD];          // Wo fp16
__device__ __half g_xrh[(size_t)MROWS * 2 * DD];       // GEMM2 A ([re|im]) fp16

// ---------------------------------------------------------------------------
// helpers
// ---------------------------------------------------------------------------
__device__ __forceinline__ uint32_t smem_to_u32(const void* p) {
    uint32_t a;
    asm("{ .reg .u64 t; cvta.to.shared.u64 t, %1; cvt.u32.u64 %0, t; }" : "=r"(a) : "l"(p));
    return a;
}
#define SWZ128(o) ((o) ^ (((o) >> 3) & 0x70))

#define CP_ASYNC16(dst, src) \
    asm volatile("cp.async.cg.shared.global [%0], [%1], 16;" :: "r"(dst), "l"(src) : "memory")
#define CP_COMMIT() asm volatile("cp.async.commit_group;" ::: "memory")
#define CP_WAIT0()  asm volatile("cp.async.wait_group 0;" ::: "memory")

__device__ __forceinline__ void ldsm4(uint32_t* r, uint32_t a) {
    asm volatile("ldmatrix.sync.aligned.m8n8.x4.shared.b16 {%0,%1,%2,%3}, [%4];"
                 : "=r"(r[0]), "=r"(r[1]), "=r"(r[2]), "=r"(r[3]) : "r"(a));
}
__device__ __forceinline__ void mma16816(float* c, const uint32_t* a, const uint32_t* b) {
    asm volatile(
        "mma.sync.aligned.m16n8k16.row.col.f32.f16.f16.f32 "
        "{%0,%1,%2,%3}, {%4,%5,%6,%7}, {%8,%9}, {%0,%1,%2,%3};"
        : "+f"(c[0]), "+f"(c[1]), "+f"(c[2]), "+f"(c[3])
        : "r"(a[0]), "r"(a[1]), "r"(a[2]), "r"(a[3]), "r"(b[0]), "r"(b[1]));
}

// ---------------------------------------------------------------------------
// Prepass: fp32 -> fp16 round, three arrays in one launch
// ---------------------------------------------------------------------------
__global__ __launch_bounds__(256) void cvt_round3(
    const float* __restrict__ s0, __half* __restrict__ d0, int n0,
    const float* __restrict__ s1, __half* __restrict__ d1, int n1,
    const float* __restrict__ s2, __half* __restrict__ d2, int n2)
{
    int i = blockIdx.x * blockDim.x + threadIdx.x;
    const float* src;
    __half* dst;
    if (i < n0)           { src = s0;  dst = d0;  }
    else if (i < n0 + n1) { src = s1;  dst = d1;  i -= n0; }
    else if (i < n0 + n1 + n2) { src = s2; dst = d2; i -= n0 + n1; }
    else return;
    float4 v = ((const float4*)src)[i];
    __half2 h[2];
    h[0] = __floats2half2_rn(v.x, v.y);
    h[1] = __floats2half2_rn(v.z, v.w);
    *(uint2*)(dst + (size_t)i * 4) = *(uint2*)h;
}

// ---------------------------------------------------------------------------
// fp16 HMMA GEMM (R8 config): C = A[M,K] @ W[N,K]^T + bias (opt ReLU/fp16 out)
// CTA 128x256, BK=128, 256 thr / 8 warps (2Mx4N), warp tile 64x64, 2-stage.
// Stage (96KB): [A0 16K | A1 16K | B0 32K | B1 32K].
// SCAN: fused chunk-local scan in the epilogue (GEMM1 only) -> g_last.
// ---------------------------------------------------------------------------
static constexpr int STAGE_B = 98304;
static constexpr int SMEM_BYTES = 2 * STAGE_B;     // 192 KB
static constexpr int SCAN_STRIDE = 516;            // odd 4B stride: conflict-free

template <bool RELU, bool HALF_OUT, bool SCAN, int K>
__global__ __launch_bounds__(256, 1) void gemm_mma(
    const __half* __restrict__ A,
    const __half* __restrict__ W,
    const float* __restrict__ bias,
    void* __restrict__ Cv,
    int N,
    const float* __restrict__ plog)
{
    extern __shared__ __align__(1024) char smem[];
    const uint32_t sbase = smem_to_u32(smem);
    const int tid = threadIdx.x;
    const int lane = tid & 31, w = tid >> 5;
    const int m0 = blockIdx.y * 128, n0 = blockIdx.x * 256;
    const int mw = (w & 1) * 64;
    const int nw = (w >> 1) * 64;

    float acc[4][8][4];
#pragma unroll
    for (int i = 0; i < 4; i++)
#pragma unroll
        for (int j = 0; j < 8; j++)
#pragma unroll
            for (int r = 0; r < 4; r++) acc[i][j][r] = 0.0f;

    const int lrow = tid >> 3;        // 0..31
    const int lsub = tid & 7;         // 0..7
    const __half* Abase = A + (size_t)(m0 + lrow) * K + lsub * 8;
    const __half* Wbase = W + (size_t)(n0 + lrow) * K + lsub * 8;
    const uint32_t ldst = SWZ128((uint32_t)(lrow * 128 + lsub * 16));

    auto issue = [&](int kt, int s) {
        const uint32_t sA = sbase + s * STAGE_B;
        const __half* as = Abase + (size_t)kt * 128;
        const __half* ws = Wbase + (size_t)kt * 128;
#pragma unroll
        for (int t = 0; t < 2; t++) {
#pragma unroll
            for (int p = 0; p < 4; p++)   // A sub-tile t
                CP_ASYNC16(sA + (uint32_t)(t * 16384) + ldst + (uint32_t)(p * 32 * 128),
                           as + t * 64 + (size_t)(p * 32) * K);
#pragma unroll
            for (int p = 0; p < 8; p++)   // B sub-tile t
                CP_ASYNC16(sA + 32768u + (uint32_t)(t * 32768) + ldst + (uint32_t)(p * 32 * 128),
                           ws + t * 64 + (size_t)(p * 32) * K);
        }
        CP_COMMIT();
    };

    auto compute = [&](int s) {
        const uint32_t sA = sbase + s * STAGE_B;
#pragma unroll
        for (int ks = 0; ks < 8; ks++) {
            const uint32_t aA = sA + (uint32_t)((ks >> 2) * 16384);
            const uint32_t aB = sA + 32768u + (uint32_t)((ks >> 2) * 32768);
            const int ksl = ks & 3;
            uint32_t a[4][4], b[4][4];
#pragma unroll
            for (int i = 0; i < 4; i++) {
                const int r = mw + i * 16 + (lane & 15);
                const uint32_t off = (uint32_t)(ksl * 32 + ((lane >> 4) << 4));
                ldsm4(a[i], aA + SWZ128((uint32_t)(r * 128) + off));
            }
#pragma unroll
            for (int jj = 0; jj < 4; jj++) {
                const int r = nw + jj * 16 + ((lane >> 4) << 3) + (lane & 7);
                const uint32_t off = (uint32_t)(ksl * 32 + (((lane >> 3) & 1) << 4));
                ldsm4(b[jj], aB + SWZ128((uint32_t)(r * 128) + off));
            }
#pragma unroll
            for (int i = 0; i < 4; i++)
#pragma unroll
                for (int jj = 0; jj < 4; jj++) {
                    mma16816(acc[i][jj * 2 + 0], a[i], b[jj] + 0);
                    mma16816(acc[i][jj * 2 + 1], a[i], b[jj] + 2);
                }
        }
    };

    constexpr int NT = K / 128;
    issue(0, 0);

#pragma unroll 1
    for (int kt = 0; kt < NT; kt++) {
        const int s = kt & 1;
        CP_WAIT0();
        __syncthreads();
        if (kt + 1 < NT) issue(kt + 1, s ^ 1);
        compute(s);
    }

    if (SCAN) __syncthreads();   // smem stages free after last compute

    // epilogue
#pragma unroll
    for (int i = 0; i < 4; i++) {
        const int mrow = m0 + mw + i * 16 + (lane >> 2);
#pragma unroll
        for (int j = 0; j < 8; j++) {
            const int ncol = n0 + nw + j * 8 + (lane & 3) * 2;
            const float b0 = bias[ncol], b1 = bias[ncol + 1];
            float2 v0 = make_float2(acc[i][j][0] + b0, acc[i][j][1] + b1);
            float2 v1 = make_float2(acc[i][j][2] + b0, acc[i][j][3] + b1);
            if (RELU) {
                v0.x = fmaxf(v0.x, 0.f); v0.y = fmaxf(v0.y, 0.f);
                v1.x = fmaxf(v1.x, 0.f); v1.y = fmaxf(v1.y, 0.f);
            }
            if (HALF_OUT) {
                __half* C = (__half*)Cv;
                __half2 h0 = __floats2half2_rn(v0.x, v0.y);
                __half2 h1 = __floats2half2_rn(v1.x, v1.y);
                *(__half2*)(C + (size_t)mrow * N + ncol) = h0;
                *(__half2*)(C + (size_t)(mrow + 8) * N + ncol) = h1;
                if (SCAN) {
                    const int lr0 = mrow - m0;
                    const int lc  = (ncol - n0) * 2;
                    *(uint32_t*)(smem + lr0 * SCAN_STRIDE + lc)       = *(uint32_t*)&h0;
                    *(uint32_t*)(smem + (lr0 + 8) * SCAN_STRIDE + lc) = *(uint32_t*)&h1;
                }
            } else {
                float* C = (float*)Cv;
                *(float2*)(C + (size_t)mrow * N + ncol) = v0;
                *(float2*)(C + (size_t)(mrow + 8) * N + ncol) = v1;
            }
        }
    }

    if (SCAN) {
        __syncthreads();
        // 256 threads = 128 dims x 2 chunks; serial 64-step scan from smem
        const int dloc = tid & 127;
        const int ch   = tid >> 7;
        const int dg   = (n0 >> 1) + dloc;

        float v  = expf(plog[dg]);
        float th = expf(plog[DD + dg]);
        float r  = expf(-v);
        float sn, cs;
        sincosf(th, &sn, &cs);
        const float lre = r * cs, lim = r * sn;

        float sre = 0.f, sim = 0.f;
        const uint32_t base = (uint32_t)((ch * 64) * SCAN_STRIDE + dloc * 4);
#pragma unroll 4
        for (int j = 0; j < 64; j++) {
            uint32_t raw = *(uint32_t*)(smem + base + j * SCAN_STRIDE);
            float2 uu = __half22float2(*(__half2*)&raw);
            float nr = fmaf(lre, sre, fmaf(-lim, sim, uu.x));
            float ni = fmaf(lre, sim, fmaf( lim, sre, uu.y));
            sre = nr; sim = ni;
        }
        const int b  = m0 >> 12;                  // /4096
        const int cg = ((m0 & 4095) >> 6) + ch;   // chunk index
        g_last[(size_t)(b * NCH + cg) * DD + dg] = make_float2(sre, sim);
    }
}

// ---------------------------------------------------------------------------
// Scan phase 2: warp-parallel Kogge-Stone carry scan (one warp per (b,d)).
// ---------------------------------------------------------------------------
__global__ __launch_bounds__(256) void scan_carry(const float* __restrict__ plog)
{
    int gw   = (blockIdx.x * blockDim.x + threadIdx.x) >> 5;
    int lane = threadIdx.x & 31;
    if (gw >= BSZ * DD) return;
    int d = gw % DD;
    int b = gw / DD;

    float v  = expf(plog[d]);
    float th = expf(plog[DD + d]);
    float Lr = expf(-(float)CH * v);
    float sn, cs;
    sincosf((float)CH * th, &sn, &cs);
    float Lre = Lr * cs, Lim = Lr * sn;

    const int k0 = lane * 2;
    const size_t idx0 = (size_t)(b * NCH + k0) * DD + d;
    float2 l0 = g_last[idx0];
    float2 l1 = g_last[idx0 + DD];

    float tre = fmaf(Lre, l0.x, fmaf(-Lim, l0.y, l1.x));
    float tim = fmaf(Lre, l0.y, fmaf( Lim, l0.x, l1.y));

    float cre = Lre * Lre - Lim * Lim;
    float cim = 2.0f * Lre * Lim;
    float xre = tre, xim = tim;
    float pre = cre, pim = cim;
#pragma unroll
    for (int i = 0; i < 5; i++) {
        float yre = __shfl_up_sync(0xffffffffu, xre, 1 << i);
        float yim = __shfl_up_sync(0xffffffffu, xim, 1 << i);
        if (lane >= (1 << i)) {
            xre = fmaf(pre, yre, fmaf(-pim, yim, xre));
            xim = fmaf(pre, yim, fmaf( pim, yre, xim));
        }
        float nre = pre * pre - pim * pim;
        pim = 2.0f * pre * pim;
        pre = nre;
    }
    float sre = __shfl_up_sync(0xffffffffu, xre, 1);
    float sim = __shfl_up_sync(0xffffffffu, xim, 1);
    if (lane == 0) { sre = 0.f; sim = 0.f; }

    g_cin[idx0] = make_float2(sre, sim);
    float c1re = fmaf(Lre, sre, fmaf(-Lim, sim, l0.x));
    float c1im = fmaf(Lre, sim, fmaf( Lim, sre, l0.y));
    g_cin[idx0 + DD] = make_float2(c1re, c1im);
}

// ---------------------------------------------------------------------------
// Scan phase 3: recompute local scan + carry + gamma, write fp16 [re|im]
// ---------------------------------------------------------------------------
__global__ __launch_bounds__(256) void scan_fix(const float* __restrict__ plog)
{
    int t = blockIdx.x * blockDim.x + threadIdx.x;
    int dh = t % (DD / 2);
    int c  = (t / (DD / 2)) % NCH;
    int b  = t / ((DD / 2) * NCH);
    int d0 = dh * 2;

    float v0 = expf(plog[d0]),      v1 = expf(plog[d0 + 1]);
    float t0 = expf(plog[DD + d0]), t1 = expf(plog[DD + d0 + 1]);
    float g0 = expf(plog[2 * DD + d0]), g1 = expf(plog[2 * DD + d0 + 1]);
    float r0 = expf(-v0), r1 = expf(-v1);
    float s0, c0s, s1, c1s;
    sincosf(t0, &s0, &c0s);
    sincosf(t1, &s1, &c1s);
    float lre0 = r0 * c0s, lim0 = r0 * s0;
    float lre1 = r1 * c1s, lim1 = r1 * s1;

    float4 cin = *(const float4*)(g_cin + (size_t)(b * NCH + c) * DD + d0);
    float pre0 = lre0, pim0 = lim0;
    float pre1 = lre1, pim1 = lim1;

    size_t base  = ((size_t)(b * LSEQ + c * CH)) * (2 * DD) + 2 * d0;
    size_t rbase = ((size_t)(b * LSEQ + c * CH)) * (2 * DD);

    float4 s = make_float4(0.f, 0.f, 0.f, 0.f);
#pragma unroll 4
    for (int j = 0; j < CH; j++) {
        uint2 raw = *(const uint2*)(g_uh + base + (size_t)j * (2 * DD));
        float2 u0 = __half22float2(*(__half2*)&raw.x);
        float2 u1 = __half22float2(*(__half2*)&raw.y);
        float a0 = fmaf(lre0, s.x, fmaf(-lim0, s.y, u0.x));
        float a1 = fmaf(lre0, s.y, fmaf( lim0, s.x, u0.y));
        float a2 = fmaf(lre1, s.z, fmaf(-lim1, s.w, u1.x));
        float a3 = fmaf(lre1, s.w, fmaf( lim1, s.z, u1.y));
        s = make_float4(a0, a1, a2, a3);

        float xre0 = g0 * (s.x + pre0 * cin.x - pim0 * cin.y);
        float xim0 = g0 * (s.y + pre0 * cin.y + pim0 * cin.x);
        float xre1 = g1 * (s.z + pre1 * cin.z - pim1 * cin.w);
        float xim1 = g1 * (s.w + pre1 * cin.w + pim1 * cin.z);
        size_t o = rbase + (size_t)j * (2 * DD) + d0;
        __half2 hre = __floats2half2_rn(xre0, xre1);
        __half2 him = __floats2half2_rn(xim0, xim1);
        *(uint32_t*)(g_xrh + o)      = *(uint32_t*)&hre;
        *(uint32_t*)(g_xrh + o + DD) = *(uint32_t*)&him;

        float n0 = pre0 * lre0 - pim0 * lim0;
        pim0 = pre0 * lim0 + pim0 * lre0; pre0 = n0;
        float n1 = pre1 * lre1 - pim1 * lim1;
        pim1 = pre1 * lim1 + pim1 * lre1; pre1 = n1;
    }
}

// ---------------------------------------------------------------------------
extern "C" void kernel_launch(void* const* d_in, const int* in_sizes, int n_in,
                              void* d_out, int out_size)
{
    const float* inputs = (const float*)d_in[0];
    const float* Wi     = (const float*)d_in[1];
    const float* bi     = (const float*)d_in[2];
    const float* Wo     = (const float*)d_in[3];
    const float* bo     = (const float*)d_in[4];
    const float* plog   = (const float*)d_in[5];

    void *uh, *ih, *wih, *woh, *xh;
    cudaGetSymbolAddress(&uh,  g_uh);
    cudaGetSymbolAddress(&ih,  g_inh);
    cudaGetSymbolAddress(&wih, g_wih);
    cudaGetSymbolAddress(&woh, g_woh);
    cudaGetSymbolAddress(&xh,  g_xrh);

    cudaFuncSetAttribute(gemm_mma<false, true, true, DD>,
                         cudaFuncAttributeMaxDynamicSharedMemorySize, SMEM_BYTES);
    cudaFuncSetAttribute(gemm_mma<true, false, false, 2 * DD>,
                         cudaFuncAttributeMaxDynamicSharedMemorySize, SMEM_BYTES);

    // prepass: fp32 -> fp16 (inputs, Wi, Wo in one launch)
    {
        const int nIn = MROWS * DD / 4;
        const int nW  = 2 * DD * DD / 4;
        const int tot = nIn + 2 * nW;
        cvt_round3<<<(tot + 255) / 256, 256>>>(
            inputs, (__half*)ih,  nIn,
            Wi,     (__half*)wih, nW,
            Wo,     (__half*)woh, nW);
    }

    // GEMM1 (+fused local scan): u = inputs @ Wi^T + bi -> g_uh, g_last
    gemm_mma<false, true, true, DD><<<dim3((2 * DD) / 256, MROWS / 128), 256, SMEM_BYTES>>>(
        (const __half*)ih, (const __half*)wih, bi, uh, 2 * DD, plog);

    // Scan: carry + fixup
    scan_carry<<<(BSZ * DD * 32) / 256, 256>>>(plog);
    scan_fix<<<(BSZ * NCH * DD / 2) / 256, 256>>>(plog);

    // GEMM2: out = relu(xr @ Wo^T + bo)
    gemm_mma<true, false, false, 2 * DD><<<dim3(DD / 256, MROWS / 128), 256, SMEM_BYTES>>>(
        (const __half*)xh, (const __half*)woh, bo, d_out, DD, nullptr);
}

// round 15
// speedup vs baseline: 1.0120x; 1.0120x over previous
#include <cuda_runtime.h>
#include <cuda_fp16.h>
#include <math.h>
#include <cstdint>

#define BSZ 4
#define LSEQ 4096
#define DD 1024
#define CH 64
#define NCH (LSEQ / CH)
#define MROWS (BSZ * LSEQ)

// ---------------------------------------------------------------------------
// Scratch (device globals)
// ---------------------------------------------------------------------------
__device__ __half g_uh[(size_t)MROWS * 2 * DD];        // GEMM1 out, fp16 interleaved complex
__device__ float2 g_last[BSZ * NCH * DD];
__device__ float2 g_cin[BSZ * NCH * DD];

__device__ __half g_inh[(size_t)MROWS * DD];           // inputs fp16
__device__ __half g_wih[(size_t)2 * DD * DD];          // Wi fp16
__device__ __half g_woh[(size_t)DD * 2 * DD];          // Wo fp16
__device__ __half g_xrh[(size_t)MROWS * 2 * DD];       // GEMM2 A ([re|im]) fp16

// ---------------------------------------------------------------------------
// helpers
// ---------------------------------------------------------------------------
__device__ __forceinline__ uint32_t smem_to_u32(const void* p) {
    uint32_t a;
    asm("{ .reg .u64 t; cvta.to.shared.u64 t, %1; cvt.u32.u64 %0, t; }" : "=r"(a) : "l"(p));
    return a;
}
#define SWZ128(o) ((o) ^ (((o) >> 3) & 0x70))

#define CP_ASYNC16(dst, src) \
    asm volatile("cp.async.cg.shared.global [%0], [%1], 16;" :: "r"(dst), "l"(src) : "memory")
#define CP_COMMIT() asm volatile("cp.async.commit_group;" ::: "memory")
#define CP_WAIT0()  asm volatile("cp.async.wait_group 0;" ::: "memory")

__device__ __forceinline__ void ldsm4(uint32_t* r, uint32_t a) {
    asm volatile("ldmatrix.sync.aligned.m8n8.x4.shared.b16 {%0,%1,%2,%3}, [%4];"
                 : "=r"(r[0]), "=r"(r[1]), "=r"(r[2]), "=r"(r[3]) : "r"(a));
}
__device__ __forceinline__ void mma16816(float* c, const uint32_t* a, const uint32_t* b) {
    asm volatile(
        "mma.sync.aligned.m16n8k16.row.col.f32.f16.f16.f32 "
        "{%0,%1,%2,%3}, {%4,%5,%6,%7}, {%8,%9}, {%0,%1,%2,%3};"
        : "+f"(c[0]), "+f"(c[1]), "+f"(c[2]), "+f"(c[3])
        : "r"(a[0]), "r"(a[1]), "r"(a[2]), "r"(a[3]), "r"(b[0]), "r"(b[1]));
}

// ---------------------------------------------------------------------------
// Prepass: fp32 -> fp16 round, three arrays in one launch
// ---------------------------------------------------------------------------
__global__ __launch_bounds__(256) void cvt_round3(
    const float* __restrict__ s0, __half* __restrict__ d0, int n0,
    const float* __restrict__ s1, __half* __restrict__ d1, int n1,
    const float* __restrict__ s2, __half* __restrict__ d2, int n2)
{
    int i = blockIdx.x * blockDim.x + threadIdx.x;
    const float* src;
    __half* dst;
    if (i < n0)           { src = s0;  dst = d0;  }
    else if (i < n0 + n1) { src = s1;  dst = d1;  i -= n0; }
    else if (i < n0 + n1 + n2) { src = s2; dst = d2; i -= n0 + n1; }
    else return;
    float4 v = ((const float4*)src)[i];
    __half2 h[2];
    h[0] = __floats2half2_rn(v.x, v.y);
    h[1] = __floats2half2_rn(v.z, v.w);
    *(uint2*)(dst + (size_t)i * 4) = *(uint2*)h;
}

// ---------------------------------------------------------------------------
// fp16 HMMA GEMM (R8 config): C = A[M,K] @ W[N,K]^T + bias (opt ReLU/fp16 out)
// CTA 128x256, BK=128, 256 thr / 8 warps (2Mx4N), warp tile 64x64, 2-stage.
// Stage (96KB): [A0 16K | A1 16K | B0 32K | B1 32K].
// ---------------------------------------------------------------------------
static constexpr int STAGE_B = 98304;
static constexpr int SMEM_BYTES = 2 * STAGE_B;   // 192 KB

template <bool RELU, bool HALF_OUT, int K>
__global__ __launch_bounds__(256, 1) void gemm_mma(
    const __half* __restrict__ A,
    const __half* __restrict__ W,
    const float* __restrict__ bias,
    void* __restrict__ Cv,
    int N)
{
    extern __shared__ __align__(1024) char smem[];
    const uint32_t sbase = smem_to_u32(smem);
    const int tid = threadIdx.x;
    const int lane = tid & 31, w = tid >> 5;
    const int m0 = blockIdx.y * 128, n0 = blockIdx.x * 256;
    const int mw = (w & 1) * 64;
    const int nw = (w >> 1) * 64;

    float acc[4][8][4];
#pragma unroll
    for (int i = 0; i < 4; i++)
#pragma unroll
        for (int j = 0; j < 8; j++)
#pragma unroll
            for (int r = 0; r < 4; r++) acc[i][j][r] = 0.0f;

    const int lrow = tid >> 3;        // 0..31
    const int lsub = tid & 7;         // 0..7
    const __half* Abase = A + (size_t)(m0 + lrow) * K + lsub * 8;
    const __half* Wbase = W + (size_t)(n0 + lrow) * K + lsub * 8;
    const uint32_t ldst = SWZ128((uint32_t)(lrow * 128 + lsub * 16));

    auto issue = [&](int kt, int s) {
        const uint32_t sA = sbase + s * STAGE_B;
        const __half* as = Abase + (size_t)kt * 128;
        const __half* ws = Wbase + (size_t)kt * 128;
#pragma unroll
        for (int t = 0; t < 2; t++) {
#pragma unroll
            for (int p = 0; p < 4; p++)   // A sub-tile t
                CP_ASYNC16(sA + (uint32_t)(t * 16384) + ldst + (uint32_t)(p * 32 * 128),
                           as + t * 64 + (size_t)(p * 32) * K);
#pragma unroll
            for (int p = 0; p < 8; p++)   // B sub-tile t
                CP_ASYNC16(sA + 32768u + (uint32_t)(t * 32768) + ldst + (uint32_t)(p * 32 * 128),
                           ws + t * 64 + (size_t)(p * 32) * K);
        }
        CP_COMMIT();
    };

    auto compute = [&](int s) {
        const uint32_t sA = sbase + s * STAGE_B;
#pragma unroll
        for (int ks = 0; ks < 8; ks++) {
            const uint32_t aA = sA + (uint32_t)((ks >> 2) * 16384);
            const uint32_t aB = sA + 32768u + (uint32_t)((ks >> 2) * 32768);
            const int ksl = ks & 3;
            uint32_t a[4][4], b[4][4];
#pragma unroll
            for (int i = 0; i < 4; i++) {
                const int r = mw + i * 16 + (lane & 15);
                const uint32_t off = (uint32_t)(ksl * 32 + ((lane >> 4) << 4));
                ldsm4(a[i], aA + SWZ128((uint32_t)(r * 128) + off));
            }
#pragma unroll
            for (int jj = 0; jj < 4; jj++) {
                const int r = nw + jj * 16 + ((lane >> 4) << 3) + (lane & 7);
                const uint32_t off = (uint32_t)(ksl * 32 + (((lane >> 3) & 1) << 4));
                ldsm4(b[jj], aB + SWZ128((uint32_t)(r * 128) + off));
            }
#pragma unroll
            for (int i = 0; i < 4; i++)
#pragma unroll
                for (int jj = 0; jj < 4; jj++) {
                    mma16816(acc[i][jj * 2 + 0], a[i], b[jj] + 0);
                    mma16816(acc[i][jj * 2 + 1], a[i], b[jj] + 2);
                }
        }
    };

    constexpr int NT = K / 128;
    issue(0, 0);

#pragma unroll 1
    for (int kt = 0; kt < NT; kt++) {
        const int s = kt & 1;
        CP_WAIT0();
        __syncthreads();
        if (kt + 1 < NT) issue(kt + 1, s ^ 1);
        compute(s);
    }

    // epilogue
#pragma unroll
    for (int i = 0; i < 4; i++) {
        const int mrow = m0 + mw + i * 16 + (lane >> 2);
#pragma unroll
        for (int j = 0; j < 8; j++) {
            const int ncol = n0 + nw + j * 8 + (lane & 3) * 2;
            const float b0 = bias[ncol], b1 = bias[ncol + 1];
            float2 v0 = make_float2(acc[i][j][0] + b0, acc[i][j][1] + b1);
            float2 v1 = make_float2(acc[i][j][2] + b0, acc[i][j][3] + b1);
            if (RELU) {
                v0.x = fmaxf(v0.x, 0.f); v0.y = fmaxf(v0.y, 0.f);
                v1.x = fmaxf(v1.x, 0.f); v1.y = fmaxf(v1.y, 0.f);
            }
            if (HALF_OUT) {
                __half* C = (__half*)Cv;
                __half2 h0 = __floats2half2_rn(v0.x, v0.y);
                __half2 h1 = __floats2half2_rn(v1.x, v1.y);
                *(__half2*)(C + (size_t)mrow * N + ncol) = h0;
                *(__half2*)(C + (size_t)(mrow + 8) * N + ncol) = h1;
            } else {
                float* C = (float*)Cv;
                *(float2*)(C + (size_t)mrow * N + ncol) = v0;
                *(float2*)(C + (size_t)(mrow + 8) * N + ncol) = v1;
            }
        }
    }
}

// ---------------------------------------------------------------------------
// Scan phase 1: local scan over fp16 u; keep only chunk-final state.
// 2 complex dims per thread (R13 config).
// ---------------------------------------------------------------------------
__global__ __launch_bounds__(256) void scan_local(const float* __restrict__ plog)
{
    int t = blockIdx.x * blockDim.x + threadIdx.x;
    int dh = t % (DD / 2);
    int c  = (t / (DD / 2)) % NCH;
    int b  = t / ((DD / 2) * NCH);
    int d0 = dh * 2;

    float v0 = expf(plog[d0]),      v1 = expf(plog[d0 + 1]);
    float t0 = expf(plog[DD + d0]), t1 = expf(plog[DD + d0 + 1]);
    float r0 = expf(-v0), r1 = expf(-v1);
    float s0, c0s, s1, c1s;
    sincosf(t0, &s0, &c0s);
    sincosf(t1, &s1, &c1s);
    float lre0 = r0 * c0s, lim0 = r0 * s0;
    float lre1 = r1 * c1s, lim1 = r1 * s1;

    size_t base = ((size_t)(b * LSEQ + c * CH)) * (2 * DD) + 2 * d0;
    float4 s = make_float4(0.f, 0.f, 0.f, 0.f);
#pragma unroll 4
    for (int j = 0; j < CH; j++) {
        uint2 raw = *(const uint2*)(g_uh + base + (size_t)j * (2 * DD));
        float2 u0 = __half22float2(*(__half2*)&raw.x);
        float2 u1 = __half22float2(*(__half2*)&raw.y);
        float a0 = fmaf(lre0, s.x, fmaf(-lim0, s.y, u0.x));
        float a1 = fmaf(lre0, s.y, fmaf( lim0, s.x, u0.y));
        float a2 = fmaf(lre1, s.z, fmaf(-lim1, s.w, u1.x));
        float a3 = fmaf(lre1, s.w, fmaf( lim1, s.z, u1.y));
        s = make_float4(a0, a1, a2, a3);
    }
    *(float4*)(g_last + (size_t)(b * NCH + c) * DD + d0) = s;
}

// ---------------------------------------------------------------------------
// Scan phase 2: warp-parallel Kogge-Stone carry scan (one warp per (b,d)).
// ---------------------------------------------------------------------------
__global__ __launch_bounds__(256) void scan_carry(const float* __restrict__ plog)
{
    int gw   = (blockIdx.x * blockDim.x + threadIdx.x) >> 5;
    int lane = threadIdx.x & 31;
    if (gw >= BSZ * DD) return;
    int d = gw % DD;
    int b = gw / DD;

    float v  = expf(plog[d]);
    float th = expf(plog[DD + d]);
    float Lr = expf(-(float)CH * v);
    float sn, cs;
    sincosf((float)CH * th, &sn, &cs);
    float Lre = Lr * cs, Lim = Lr * sn;

    const int k0 = lane * 2;
    const size_t idx0 = (size_t)(b * NCH + k0) * DD + d;
    float2 l0 = g_last[idx0];
    float2 l1 = g_last[idx0 + DD];

    float tre = fmaf(Lre, l0.x, fmaf(-Lim, l0.y, l1.x));
    float tim = fmaf(Lre, l0.y, fmaf( Lim, l0.x, l1.y));

    float cre = Lre * Lre - Lim * Lim;
    float cim = 2.0f * Lre * Lim;
    float xre = tre, xim = tim;
    float pre = cre, pim = cim;
#pragma unroll
    for (int i = 0; i < 5; i++) {
        float yre = __shfl_up_sync(0xffffffffu, xre, 1 << i);
        float yim = __shfl_up_sync(0xffffffffu, xim, 1 << i);
        if (lane >= (1 << i)) {
            xre = fmaf(pre, yre, fmaf(-pim, yim, xre));
            xim = fmaf(pre, yim, fmaf( pim, yre, xim));
        }
        float nre = pre * pre - pim * pim;
        pim = 2.0f * pre * pim;
        pre = nre;
    }
    float sre = __shfl_up_sync(0xffffffffu, xre, 1);
    float sim = __shfl_up_sync(0xffffffffu, xim, 1);
    if (lane == 0) { sre = 0.f; sim = 0.f; }

    g_cin[idx0] = make_float2(sre, sim);
    float c1re = fmaf(Lre, sre, fmaf(-Lim, sim, l0.x));
    float c1im = fmaf(Lre, sim, fmaf( Lim, sre, l0.y));
    g_cin[idx0 + DD] = make_float2(c1re, c1im);
}

// ---------------------------------------------------------------------------
// Scan phase 3: recompute local scan + carry + gamma, write fp16 [re|im].
// ONE complex dim per thread -> grid 1024 (better occupancy / wave balance).
// ---------------------------------------------------------------------------
__global__ __launch_bounds__(256) void scan_fix(const float* __restrict__ plog)
{
    int t = blockIdx.x * blockDim.x + threadIdx.x;   // B*NCH*DD threads
    int d = t % DD;
    int c = (t / DD) % NCH;
    int b = t / (DD * NCH);

    float v  = expf(plog[d]);
    float th = expf(plog[DD + d]);
    float g  = expf(plog[2 * DD + d]);
    float r  = expf(-v);
    float sn, cs;
    sincosf(th, &sn, &cs);
    const float lre = r * cs, lim = r * sn;

    float2 cin = g_cin[(size_t)(b * NCH + c) * DD + d];
    float pre = lre, pim = lim;

    size_t base  = ((size_t)(b * LSEQ + c * CH)) * (2 * DD) + 2 * d;
    size_t rbase = ((size_t)(b * LSEQ + c * CH)) * (2 * DD);

    float sre = 0.f, sim = 0.f;
#pragma unroll 4
    for (int j = 0; j < CH; j++) {
        uint32_t raw = *(const uint32_t*)(g_uh + base + (size_t)j * (2 * DD));
        float2 u = __half22float2(*(__half2*)&raw);
        float nr = fmaf(lre, sre, fmaf(-lim, sim, u.x));
        float ni = fmaf(lre, sim, fmaf( lim, sre, u.y));
        sre = nr; sim = ni;

        float xre = g * (sre + pre * cin.x - pim * cin.y);
        float xim = g * (sim + pre * cin.y + pim * cin.x);
        size_t o = rbase + (size_t)j * (2 * DD) + d;
        g_xrh[o]      = __float2half(xre);
        g_xrh[o + DD] = __float2half(xim);

        float n0 = pre * lre - pim * lim;
        pim = pre * lim + pim * lre;
        pre = n0;
    }
}

// ---------------------------------------------------------------------------
extern "C" void kernel_launch(void* const* d_in, const int* in_sizes, int n_in,
                              void* d_out, int out_size)
{
    const float* inputs = (const float*)d_in[0];
    const float* Wi     = (const float*)d_in[1];
    const float* bi     = (const float*)d_in[2];
    const float* Wo     = (const float*)d_in[3];
    const float* bo     = (const float*)d_in[4];
    const float* plog   = (const float*)d_in[5];

    void *uh, *ih, *wih, *woh, *xh;
    cudaGetSymbolAddress(&uh,  g_uh);
    cudaGetSymbolAddress(&ih,  g_inh);
    cudaGetSymbolAddress(&wih, g_wih);
    cudaGetSymbolAddress(&woh, g_woh);
    cudaGetSymbolAddress(&xh,  g_xrh);

    cudaFuncSetAttribute(gemm_mma<false, true, DD>,
                         cudaFuncAttributeMaxDynamicSharedMemorySize, SMEM_BYTES);
    cudaFuncSetAttribute(gemm_mma<true, false, 2 * DD>,
                         cudaFuncAttributeMaxDynamicSharedMemorySize, SMEM_BYTES);

    // prepass: fp32 -> fp16 (inputs, Wi, Wo in one launch)
    {
        const int nIn = MROWS * DD / 4;
        const int nW  = 2 * DD * DD / 4;
        const int tot = nIn + 2 * nW;
        cvt_round3<<<(tot + 255) / 256, 256>>>(
            inputs, (__half*)ih,  nIn,
            Wi,     (__half*)wih, nW,
            Wo,     (__half*)woh, nW);
    }

    // GEMM1: u = inputs @ Wi^T + bi  -> g_uh (fp16)
    gemm_mma<false, true, DD><<<dim3((2 * DD) / 256, MROWS / 128), 256, SMEM_BYTES>>>(
        (const __half*)ih, (const __half*)wih, bi, uh, 2 * DD);

    // Scan
    scan_local<<<(BSZ * NCH * DD / 2) / 256, 256>>>(plog);
    scan_carry<<<(BSZ * DD * 32) / 256, 256>>>(plog);
    scan_fix<<<(BSZ * NCH * DD) / 256, 256>>>(plog);

    // GEMM2: out = relu(xr @ Wo^T + bo)
    gemm_mma<true, false, 2 * DD><<<dim3(DD / 256, MROWS / 128), 256, SMEM_BYTES>>>(
        (const __half*)xh, (const __half*)woh, bo, d_out, DD);
}

// round 16
// speedup vs baseline: 1.0545x; 1.0419x over previous
#include <cuda_runtime.h>
#include <cuda_fp16.h>
#include <math.h>
#include <cstdint>

#define BSZ 4
#define LSEQ 4096
#define DD 1024
#define CH 64
#define NCH (LSEQ / CH)
#define MROWS (BSZ * LSEQ)

// ---------------------------------------------------------------------------
// Scratch (device globals)
// ---------------------------------------------------------------------------
__device__ __half g_uh[(size_t)MROWS * 2 * DD];        // GEMM1 out, fp16 interleaved complex
__device__ float2 g_last[BSZ * NCH * DD];
__device__ float2 g_cin[BSZ * NCH * DD];

__device__ __half g_inh[(size_t)MROWS * DD];           // inputs fp16
__device__ __half g_wih[(size_t)2 * DD * DD];          // Wi fp16
__device__ __half g_woh[(size_t)DD * 2 * DD];          // Wo fp16
__device__ __half g_xrh[(size_t)MROWS * 2 * DD];       // GEMM2 A ([re|im]) fp16

// ---------------------------------------------------------------------------
// helpers
// ---------------------------------------------------------------------------
__device__ __forceinline__ uint32_t smem_to_u32(const void* p) {
    uint32_t a;
    asm("{ .reg .u64 t; cvta.to.shared.u64 t, %1; cvt.u32.u64 %0, t; }" : "=r"(a) : "l"(p));
    return a;
}
#define SWZ128(o) ((o) ^ (((o) >> 3) & 0x70))

#define CP_ASYNC16(dst, src) \
    asm volatile("cp.async.cg.shared.global [%0], [%1], 16;" :: "r"(dst), "l"(src) : "memory")
#define CP_COMMIT() asm volatile("cp.async.commit_group;" ::: "memory")
#define CP_WAIT0()  asm volatile("cp.async.wait_group 0;" ::: "memory")

__device__ __forceinline__ void ldsm4(uint32_t* r, uint32_t a) {
    asm volatile("ldmatrix.sync.aligned.m8n8.x4.shared.b16 {%0,%1,%2,%3}, [%4];"
                 : "=r"(r[0]), "=r"(r[1]), "=r"(r[2]), "=r"(r[3]) : "r"(a));
}
__device__ __forceinline__ void mma16816(float* c, const uint32_t* a, const uint32_t* b) {
    asm volatile(
        "mma.sync.aligned.m16n8k16.row.col.f32.f16.f16.f32 "
        "{%0,%1,%2,%3}, {%4,%5,%6,%7}, {%8,%9}, {%0,%1,%2,%3};"
        : "+f"(c[0]), "+f"(c[1]), "+f"(c[2]), "+f"(c[3])
        : "r"(a[0]), "r"(a[1]), "r"(a[2]), "r"(a[3]), "r"(b[0]), "r"(b[1]));
}

// ---------------------------------------------------------------------------
// Prepass: fp32 -> fp16 round, three arrays in one launch
// ---------------------------------------------------------------------------
__global__ __launch_bounds__(256) void cvt_round3(
    const float* __restrict__ s0, __half* __restrict__ d0, int n0,
    const float* __restrict__ s1, __half* __restrict__ d1, int n1,
    const float* __restrict__ s2, __half* __restrict__ d2, int n2)
{
    int i = blockIdx.x * blockDim.x + threadIdx.x;
    const float* src;
    __half* dst;
    if (i < n0)           { src = s0;  dst = d0;  }
    else if (i < n0 + n1) { src = s1;  dst = d1;  i -= n0; }
    else if (i < n0 + n1 + n2) { src = s2; dst = d2; i -= n0 + n1; }
    else return;
    float4 v = ((const float4*)src)[i];
    __half2 h[2];
    h[0] = __floats2half2_rn(v.x, v.y);
    h[1] = __floats2half2_rn(v.z, v.w);
    *(uint2*)(dst + (size_t)i * 4) = *(uint2*)h;
}

// ---------------------------------------------------------------------------
// fp16 HMMA GEMM (R8 config): C = A[M,K] @ W[N,K]^T + bias (opt ReLU/fp16 out)
// CTA 128x256, BK=128, 256 thr / 8 warps (2Mx4N), warp tile 64x64, 2-stage.
// Stage (96KB): [A0 16K | A1 16K | B0 32K | B1 32K].
// ---------------------------------------------------------------------------
static constexpr int STAGE_B = 98304;
static constexpr int SMEM_BYTES = 2 * STAGE_B;   // 192 KB

template <bool RELU, bool HALF_OUT, int K>
__global__ __launch_bounds__(256, 1) void gemm_mma(
    const __half* __restrict__ A,
    const __half* __restrict__ W,
    const float* __restrict__ bias,
    void* __restrict__ Cv,
    int N)
{
    extern __shared__ __align__(1024) char smem[];
    const uint32_t sbase = smem_to_u32(smem);
    const int tid = threadIdx.x;
    const int lane = tid & 31, w = tid >> 5;
    const int m0 = blockIdx.y * 128, n0 = blockIdx.x * 256;
    const int mw = (w & 1) * 64;
    const int nw = (w >> 1) * 64;

    float acc[4][8][4];
#pragma unroll
    for (int i = 0; i < 4; i++)
#pragma unroll
        for (int j = 0; j < 8; j++)
#pragma unroll
            for (int r = 0; r < 4; r++) acc[i][j][r] = 0.0f;

    const int lrow = tid >> 3;        // 0..31
    const int lsub = tid & 7;         // 0..7
    const __half* Abase = A + (size_t)(m0 + lrow) * K + lsub * 8;
    const __half* Wbase = W + (size_t)(n0 + lrow) * K + lsub * 8;
    const uint32_t ldst = SWZ128((uint32_t)(lrow * 128 + lsub * 16));

    auto issue = [&](int kt, int s) {
        const uint32_t sA = sbase + s * STAGE_B;
        const __half* as = Abase + (size_t)kt * 128;
        const __half* ws = Wbase + (size_t)kt * 128;
#pragma unroll
        for (int t = 0; t < 2; t++) {
#pragma unroll
            for (int p = 0; p < 4; p++)   // A sub-tile t
                CP_ASYNC16(sA + (uint32_t)(t * 16384) + ldst + (uint32_t)(p * 32 * 128),
                           as + t * 64 + (size_t)(p * 32) * K);
#pragma unroll
            for (int p = 0; p < 8; p++)   // B sub-tile t
                CP_ASYNC16(sA + 32768u + (uint32_t)(t * 32768) + ldst + (uint32_t)(p * 32 * 128),
                           ws + t * 64 + (size_t)(p * 32) * K);
        }
        CP_COMMIT();
    };

    auto compute = [&](int s) {
        const uint32_t sA = sbase + s * STAGE_B;
#pragma unroll
        for (int ks = 0; ks < 8; ks++) {
            const uint32_t aA = sA + (uint32_t)((ks >> 2) * 16384);
            const uint32_t aB = sA + 32768u + (uint32_t)((ks >> 2) * 32768);
            const int ksl = ks & 3;
            uint32_t a[4][4], b[4][4];
#pragma unroll
            for (int i = 0; i < 4; i++) {
                const int r = mw + i * 16 + (lane & 15);
                const uint32_t off = (uint32_t)(ksl * 32 + ((lane >> 4) << 4));
                ldsm4(a[i], aA + SWZ128((uint32_t)(r * 128) + off));
            }
#pragma unroll
            for (int jj = 0; jj < 4; jj++) {
                const int r = nw + jj * 16 + ((lane >> 4) << 3) + (lane & 7);
                const uint32_t off = (uint32_t)(ksl * 32 + (((lane >> 3) & 1) << 4));
                ldsm4(b[jj], aB + SWZ128((uint32_t)(r * 128) + off));
            }
#pragma unroll
            for (int i = 0; i < 4; i++)
#pragma unroll
                for (int jj = 0; jj < 4; jj++) {
                    mma16816(acc[i][jj * 2 + 0], a[i], b[jj] + 0);
                    mma16816(acc[i][jj * 2 + 1], a[i], b[jj] + 2);
                }
        }
    };

    constexpr int NT = K / 128;
    issue(0, 0);

#pragma unroll 1
    for (int kt = 0; kt < NT; kt++) {
        const int s = kt & 1;
        CP_WAIT0();
        __syncthreads();
        if (kt + 1 < NT) issue(kt + 1, s ^ 1);
        compute(s);
    }

    // epilogue
#pragma unroll
    for (int i = 0; i < 4; i++) {
        const int mrow = m0 + mw + i * 16 + (lane >> 2);
#pragma unroll
        for (int j = 0; j < 8; j++) {
            const int ncol = n0 + nw + j * 8 + (lane & 3) * 2;
            const float b0 = bias[ncol], b1 = bias[ncol + 1];
            float2 v0 = make_float2(acc[i][j][0] + b0, acc[i][j][1] + b1);
            float2 v1 = make_float2(acc[i][j][2] + b0, acc[i][j][3] + b1);
            if (RELU) {
                v0.x = fmaxf(v0.x, 0.f); v0.y = fmaxf(v0.y, 0.f);
                v1.x = fmaxf(v1.x, 0.f); v1.y = fmaxf(v1.y, 0.f);
            }
            if (HALF_OUT) {
                __half* C = (__half*)Cv;
                __half2 h0 = __floats2half2_rn(v0.x, v0.y);
                __half2 h1 = __floats2half2_rn(v1.x, v1.y);
                *(__half2*)(C + (size_t)mrow * N + ncol) = h0;
                *(__half2*)(C + (size_t)(mrow + 8) * N + ncol) = h1;
            } else {
                float* C = (float*)Cv;
                *(float2*)(C + (size_t)mrow * N + ncol) = v0;
                *(float2*)(C + (size_t)(mrow + 8) * N + ncol) = v1;
            }
        }
    }
}

// ---------------------------------------------------------------------------
// Scan phase 1: local scan over fp16 u; keep only chunk-final state.
// 2 complex dims per thread, 8-deep load prefetch (MLP 8).
// ---------------------------------------------------------------------------
__global__ __launch_bounds__(256) void scan_local(const float* __restrict__ plog)
{
    int t = blockIdx.x * blockDim.x + threadIdx.x;
    int dh = t % (DD / 2);
    int c  = (t / (DD / 2)) % NCH;
    int b  = t / ((DD / 2) * NCH);
    int d0 = dh * 2;

    float v0 = expf(plog[d0]),      v1 = expf(plog[d0 + 1]);
    float t0 = expf(plog[DD + d0]), t1 = expf(plog[DD + d0 + 1]);
    float r0 = expf(-v0), r1 = expf(-v1);
    float s0, c0s, s1, c1s;
    sincosf(t0, &s0, &c0s);
    sincosf(t1, &s1, &c1s);
    float lre0 = r0 * c0s, lim0 = r0 * s0;
    float lre1 = r1 * c1s, lim1 = r1 * s1;

    size_t base = ((size_t)(b * LSEQ + c * CH)) * (2 * DD) + 2 * d0;
    float4 s = make_float4(0.f, 0.f, 0.f, 0.f);
#pragma unroll 1
    for (int blk = 0; blk < CH / 8; blk++) {
        uint2 raw[8];
#pragma unroll
        for (int j = 0; j < 8; j++)
            raw[j] = *(const uint2*)(g_uh + base + (size_t)(blk * 8 + j) * (2 * DD));
#pragma unroll
        for (int j = 0; j < 8; j++) {
            float2 u0 = __half22float2(*(__half2*)&raw[j].x);
            float2 u1 = __half22float2(*(__half2*)&raw[j].y);
            float a0 = fmaf(lre0, s.x, fmaf(-lim0, s.y, u0.x));
            float a1 = fmaf(lre0, s.y, fmaf( lim0, s.x, u0.y));
            float a2 = fmaf(lre1, s.z, fmaf(-lim1, s.w, u1.x));
            float a3 = fmaf(lre1, s.w, fmaf( lim1, s.z, u1.y));
            s = make_float4(a0, a1, a2, a3);
        }
    }
    *(float4*)(g_last + (size_t)(b * NCH + c) * DD + d0) = s;
}

// ---------------------------------------------------------------------------
// Scan phase 2: warp-parallel Kogge-Stone carry scan (one warp per (b,d)).
// ---------------------------------------------------------------------------
__global__ __launch_bounds__(256) void scan_carry(const float* __restrict__ plog)
{
    int gw   = (blockIdx.x * blockDim.x + threadIdx.x) >> 5;
    int lane = threadIdx.x & 31;
    if (gw >= BSZ * DD) return;
    int d = gw % DD;
    int b = gw / DD;

    float v  = expf(plog[d]);
    float th = expf(plog[DD + d]);
    float Lr = expf(-(float)CH * v);
    float sn, cs;
    sincosf((float)CH * th, &sn, &cs);
    float Lre = Lr * cs, Lim = Lr * sn;

    const int k0 = lane * 2;
    const size_t idx0 = (size_t)(b * NCH + k0) * DD + d;
    float2 l0 = g_last[idx0];
    float2 l1 = g_last[idx0 + DD];

    float tre = fmaf(Lre, l0.x, fmaf(-Lim, l0.y, l1.x));
    float tim = fmaf(Lre, l0.y, fmaf( Lim, l0.x, l1.y));

    float cre = Lre * Lre - Lim * Lim;
    float cim = 2.0f * Lre * Lim;
    float xre = tre, xim = tim;
    float pre = cre, pim = cim;
#pragma unroll
    for (int i = 0; i < 5; i++) {
        float yre = __shfl_up_sync(0xffffffffu, xre, 1 << i);
        float yim = __shfl_up_sync(0xffffffffu, xim, 1 << i);
        if (lane >= (1 << i)) {
            xre = fmaf(pre, yre, fmaf(-pim, yim, xre));
            xim = fmaf(pre, yim, fmaf( pim, yre, xim));
        }
        float nre = pre * pre - pim * pim;
        pim = 2.0f * pre * pim;
        pre = nre;
    }
    float sre = __shfl_up_sync(0xffffffffu, xre, 1);
    float sim = __shfl_up_sync(0xffffffffu, xim, 1);
    if (lane == 0) { sre = 0.f; sim = 0.f; }

    g_cin[idx0] = make_float2(sre, sim);
    float c1re = fmaf(Lre, sre, fmaf(-Lim, sim, l0.x));
    float c1im = fmaf(Lre, sim, fmaf( Lim, sre, l0.y));
    g_cin[idx0 + DD] = make_float2(c1re, c1im);
}

// ---------------------------------------------------------------------------
// Scan phase 3: recompute local scan + carry + gamma, write fp16 [re|im].
// One complex dim per thread, 16-deep load prefetch (MLP 16).
// ---------------------------------------------------------------------------
__global__ __launch_bounds__(256) void scan_fix(const float* __restrict__ plog)
{
    int t = blockIdx.x * blockDim.x + threadIdx.x;   // B*NCH*DD threads
    int d = t % DD;
    int c = (t / DD) % NCH;
    int b = t / (DD * NCH);

    float v  = expf(plog[d]);
    float th = expf(plog[DD + d]);
    float g  = expf(plog[2 * DD + d]);
    float r  = expf(-v);
    float sn, cs;
    sincosf(th, &sn, &cs);
    const float lre = r * cs, lim = r * sn;

    float2 cin = g_cin[(size_t)(b * NCH + c) * DD + d];
    float pre = lre, pim = lim;

    size_t base  = ((size_t)(b * LSEQ + c * CH)) * (2 * DD) + 2 * d;
    size_t rbase = ((size_t)(b * LSEQ + c * CH)) * (2 * DD);

    float sre = 0.f, sim = 0.f;
#pragma unroll 1
    for (int blk = 0; blk < CH / 16; blk++) {
        uint32_t raw[16];
#pragma unroll
        for (int j = 0; j < 16; j++)
            raw[j] = *(const uint32_t*)(g_uh + base + (size_t)(blk * 16 + j) * (2 * DD));
#pragma unroll
        for (int j = 0; j < 16; j++) {
            float2 u = __half22float2(*(__half2*)&raw[j]);
            float nr = fmaf(lre, sre, fmaf(-lim, sim, u.x));
            float ni = fmaf(lre, sim, fmaf( lim, sre, u.y));
            sre = nr; sim = ni;

            float xre = g * (sre + pre * cin.x - pim * cin.y);
            float xim = g * (sim + pre * cin.y + pim * cin.x);
            size_t o = rbase + (size_t)(blk * 16 + j) * (2 * DD) + d;
            g_xrh[o]      = __float2half(xre);
            g_xrh[o + DD] = __float2half(xim);

            float n0 = pre * lre - pim * lim;
            pim = pre * lim + pim * lre;
            pre = n0;
        }
    }
}

// ---------------------------------------------------------------------------
extern "C" void kernel_launch(void* const* d_in, const int* in_sizes, int n_in,
                              void* d_out, int out_size)
{
    const float* inputs = (const float*)d_in[0];
    const float* Wi     = (const float*)d_in[1];
    const float* bi     = (const float*)d_in[2];
    const float* Wo     = (const float*)d_in[3];
    const float* bo     = (const float*)d_in[4];
    const float* plog   = (const float*)d_in[5];

    void *uh, *ih, *wih, *woh, *xh;
    cudaGetSymbolAddress(&uh,  g_uh);
    cudaGetSymbolAddress(&ih,  g_inh);
    cudaGetSymbolAddress(&wih, g_wih);
    cudaGetSymbolAddress(&woh, g_woh);
    cudaGetSymbolAddress(&xh,  g_xrh);

    cudaFuncSetAttribute(gemm_mma<false, true, DD>,
                         cudaFuncAttributeMaxDynamicSharedMemorySize, SMEM_BYTES);
    cudaFuncSetAttribute(gemm_mma<true, false, 2 * DD>,
                         cudaFuncAttributeMaxDynamicSharedMemorySize, SMEM_BYTES);

    // prepass: fp32 -> fp16 (inputs, Wi, Wo in one launch)
    {
        const int nIn = MROWS * DD / 4;
        const int nW  = 2 * DD * DD / 4;
        const int tot = nIn + 2 * nW;
        cvt_round3<<<(tot + 255) / 256, 256>>>(
            inputs, (__half*)ih,  nIn,
            Wi,     (__half*)wih, nW,
            Wo,     (__half*)woh, nW);
    }

    // GEMM1: u = inputs @ Wi^T + bi  -> g_uh (fp16)
    gemm_mma<false, true, DD><<<dim3((2 * DD) / 256, MROWS / 128), 256, SMEM_BYTES>>>(
        (const __half*)ih, (const __half*)wih, bi, uh, 2 * DD);

    // Scan
    scan_local<<<(BSZ * NCH * DD / 2) / 256, 256>>>(plog);
    scan_carry<<<(BSZ * DD * 32) / 256, 256>>>(plog);
    scan_fix<<<(BSZ * NCH * DD) / 256, 256>>>(plog);

    // GEMM2: out = relu(xr @ Wo^T + bo)
    gemm_mma<true, false, 2 * DD><<<dim3(DD / 256, MROWS / 128), 256, SMEM_BYTES>>>(
        (const __half*)xh, (const __half*)woh, bo, d_out, DD);
}